// round 6
// baseline (speedup 1.0000x reference)
#include <cuda_runtime.h>
#include <cuda_bf16.h>
#include <math.h>
#include <stdint.h>

#define BB 2
#define NNTOK 2048
#define DD 1024
#define HH 16
#define HDIM 64
#define BN (BB*NNTOK)

// ---------------- scratch (device globals) ----------------------------------
__device__ __nv_bfloat16 g_xhi[BN*DD], g_xlo[BN*DD];
__device__ __nv_bfloat16 g_nhi[BN*DD], g_nlo[BN*DD];
__device__ __nv_bfloat16 g_wqhi[DD*DD], g_wqlo[DD*DD];
__device__ __nv_bfloat16 g_wkhi[DD*DD], g_wklo[DD*DD];
__device__ __nv_bfloat16 g_wvhi[DD*DD], g_wvlo[DD*DD];
__device__ __nv_bfloat16 g_wohi[DD*DD], g_wolo[DD*DD];
__device__ __nv_bfloat16 g_wshi[128*DD], g_wslo[128*DD];
__device__ float g_q [BN*DD];
__device__ float g_k [BN*DD];
__device__ float g_v [BN*DD];
__device__ float g_o [BN*DD];
__device__ float g_f [BN*HH];
__device__ float g_g [BN*HH];
__device__ float g_g1[BN*HDIM];

__device__ __forceinline__ float sigmoidf_(float x) { return 1.f / (1.f + expf(-x)); }

__device__ __forceinline__ uint32_t s2u(const void* p) {
    uint32_t a;
    asm("{ .reg .u64 t; cvta.to.shared.u64 t, %1; cvt.u32.u64 %0, t; }" : "=r"(a) : "l"(p));
    return a;
}
__device__ __forceinline__ void cp16(uint32_t dst, const void* src) {
    asm volatile("cp.async.cg.shared.global [%0], [%1], 16;" :: "r"(dst), "l"(src) : "memory");
}
__device__ __forceinline__ void ldm4(uint32_t* r, uint32_t addr) {
    asm volatile("ldmatrix.sync.aligned.m8n8.x4.shared.b16 {%0,%1,%2,%3}, [%4];"
        : "=r"(r[0]), "=r"(r[1]), "=r"(r[2]), "=r"(r[3]) : "r"(addr));
}
__device__ __forceinline__ void mma16816(float* d, const uint32_t* a, const uint32_t* b) {
    asm volatile("mma.sync.aligned.m16n8k16.row.col.f32.bf16.bf16.f32 "
        "{%0,%1,%2,%3}, {%4,%5,%6,%7}, {%8,%9}, {%0,%1,%2,%3};"
        : "+f"(d[0]), "+f"(d[1]), "+f"(d[2]), "+f"(d[3])
        : "r"(a[0]), "r"(a[1]), "r"(a[2]), "r"(a[3]), "r"(b[0]), "r"(b[1]));
}

// ---------------- merged prep: conv_a + 4x conv_wT + conv_small ---------------
__global__ __launch_bounds__(256) void prep_kernel(
    const float* __restrict__ x,
    const float* __restrict__ Wq, const float* __restrict__ Wk,
    const float* __restrict__ Wv, const float* __restrict__ Wo,
    const float* __restrict__ Wg, const float* __restrict__ Wf,
    const float* __restrict__ Wg1)
{
    __shared__ float ts[32][33];
    const int bid = blockIdx.x, tid = threadIdx.x;
    if (bid < 16384) {                         // x -> hi/lo
        int i = bid * 256 + tid;
        float v = x[i];
        __nv_bfloat16 h = __float2bfloat16(v);
        g_xhi[i] = h;
        g_xlo[i] = __float2bfloat16(v - __bfloat162float(h));
    } else if (bid < 16384 + 4096) {           // 4 weight transposes
        int t = bid - 16384;
        int z = t >> 10, rem = t & 1023;
        int bx = rem & 31, by = rem >> 5;
        const float* W; __nv_bfloat16 *hi, *lo;
        switch (z) {
            case 0:  W = Wq; hi = g_wqhi; lo = g_wqlo; break;
            case 1:  W = Wk; hi = g_wkhi; lo = g_wklo; break;
            case 2:  W = Wv; hi = g_wvhi; lo = g_wvlo; break;
            default: W = Wo; hi = g_wohi; lo = g_wolo; break;
        }
        const int r = tid >> 5, c = tid & 31;
#pragma unroll
        for (int i = 0; i < 4; i++)
            ts[r + 8*i][c] = W[(size_t)(by*32 + r + 8*i) * DD + bx*32 + c];
        __syncthreads();
#pragma unroll
        for (int i = 0; i < 4; i++) {
            int n = bx*32 + r + 8*i, k = by*32 + c;
            float v = ts[c][r + 8*i];
            __nv_bfloat16 h = __float2bfloat16(v);
            hi[(size_t)n*DD + k] = h;
            lo[(size_t)n*DD + k] = __float2bfloat16(v - __bfloat162float(h));
        }
    } else {                                    // small weights, n = 0..127
        int n = bid - (16384 + 4096);
        for (int k = tid; k < DD; k += 256) {
            float v = (n < 16) ? Wg[(size_t)k*16 + n] : (n < 32) ? Wf[(size_t)k*16 + n - 16]
                    : (n < 96) ? Wg1[(size_t)k*64 + n - 32] : 0.f;
            __nv_bfloat16 h = __float2bfloat16(v);
            g_wshi[(size_t)n*DD + k] = h;
            g_wslo[(size_t)n*DD + k] = __float2bfloat16(v - __bfloat162float(h));
        }
    }
}

// ---------------- bf16 split GEMM via mma.sync + ldmatrix --------------------
// modes: 0 plain, 1 silu, 2 silu+per-head-l2norm, (tn==8 in silu launch -> scatter)
#define PITCH 80
#define ABUF (128*PITCH)
#define STG (2*ABUF)
#define GSMEM (4*STG)   /* 81920 */
__global__ __launch_bounds__(256, 2) void gemm_mma(
    const __nv_bfloat16* __restrict__ Ahi, const __nv_bfloat16* __restrict__ Alo,
    const __nv_bfloat16* __restrict__ Bhi, const __nv_bfloat16* __restrict__ Blo,
    const __nv_bfloat16* __restrict__ B2hi, const __nv_bfloat16* __restrict__ B2lo,
    float* __restrict__ C, int mode)
{
    extern __shared__ __align__(16) char sm[];
    const uint32_t sb = s2u(sm);
    const int tid = threadIdx.x, wid = tid >> 5, lane = tid & 31;
    const int wm = wid >> 2, wn = wid & 3;
    const int tn = blockIdx.x;
    const int m0 = blockIdx.y * 128;
    int md = mode, n0 = tn * 128;
    if (tn == 8) { Bhi = B2hi; Blo = B2lo; md = 3; n0 = 0; }

    float acc[4][4][4];
#pragma unroll
    for (int i = 0; i < 4; i++)
#pragma unroll
        for (int j = 0; j < 4; j++)
#pragma unroll
            for (int l = 0; l < 4; l++) acc[i][j][l] = 0.f;

    auto load_chunk = [&](int kf) {
        const int seg = kf >> 5;
        const __nv_bfloat16* Aa = (seg == 1) ? Alo : Ahi;
        const __nv_bfloat16* Ba = (seg == 2) ? Blo : Bhi;
        const int kl = (kf & 31) * 32;
        const uint32_t base = sb + (uint32_t)(kf & 3) * STG;
#pragma unroll
        for (int i = 0; i < 2; i++) {
            int idx = tid + i * 256;
            int row = idx >> 2, q = idx & 3;
            cp16(base + row * PITCH + q * 16, Aa + (size_t)(m0 + row) * DD + kl + q * 8);
            cp16(base + ABUF + row * PITCH + q * 16, Ba + (size_t)(n0 + row) * DD + kl + q * 8);
        }
        asm volatile("cp.async.commit_group;" ::: "memory");
    };

    load_chunk(0); load_chunk(1); load_chunk(2);

    // precomputed ldmatrix offsets
    const int la = lane & 15, lb8 = (lane >> 4) * 16;
    const int rb_row = ((lane >> 4) & 1) * 8 + (lane & 7);
    const int rb_col = ((lane >> 3) & 1) * 16;
    uint32_t offa[4], offb[2];
#pragma unroll
    for (int mi = 0; mi < 4; mi++) offa[mi] = (uint32_t)((wm*64 + mi*16 + la) * PITCH + lb8);
#pragma unroll
    for (int nj = 0; nj < 2; nj++) offb[nj] = (uint32_t)((wn*32 + nj*16 + rb_row) * PITCH + rb_col);

    for (int kc = 0; kc < 96; kc++) {
        asm volatile("cp.async.wait_group 2;" ::: "memory");
        __syncthreads();

        const uint32_t As = sb + (uint32_t)(kc & 3) * STG;
        const uint32_t Bs = As + ABUF;
        uint32_t a[2][4][4], b[2][4][2];
#pragma unroll
        for (int ks = 0; ks < 2; ks++) {
#pragma unroll
            for (int mi = 0; mi < 4; mi++) ldm4(a[ks][mi], As + offa[mi] + ks*32);
#pragma unroll
            for (int nj = 0; nj < 2; nj++) {
                uint32_t t[4];
                ldm4(t, Bs + offb[nj] + ks*32);
                b[ks][nj*2][0] = t[0]; b[ks][nj*2][1] = t[1];
                b[ks][nj*2+1][0] = t[2]; b[ks][nj*2+1][1] = t[3];
            }
        }
        if (kc + 3 < 96) load_chunk(kc + 3);
        else asm volatile("cp.async.commit_group;" ::: "memory");
#pragma unroll
        for (int ks = 0; ks < 2; ks++)
#pragma unroll
            for (int mi = 0; mi < 4; mi++)
#pragma unroll
                for (int ni = 0; ni < 4; ni++)
                    mma16816(acc[mi][ni], a[ks][mi], b[ks][ni]);
    }

    const int r_lo = lane >> 2, c_lo = (lane & 3) * 2;

    if (md == 1 || md == 2) {      // silu in place
#pragma unroll
        for (int mi = 0; mi < 4; mi++)
#pragma unroll
            for (int ni = 0; ni < 4; ni++)
#pragma unroll
                for (int l = 0; l < 4; l++) {
                    float z = acc[mi][ni][l];
                    acc[mi][ni][l] = z * sigmoidf_(z);
                }
    }

    float inv[4][2];               // per (mi, half) l2 scale for mode 2
#pragma unroll
    for (int mi = 0; mi < 4; mi++) { inv[mi][0] = 1.f; inv[mi][1] = 1.f; }

    if (md == 2) {
        __syncthreads();           // mainloop smem reads done everywhere
        float* red = (float*)sm;   // [128][4]
#pragma unroll
        for (int mi = 0; mi < 4; mi++) {
#pragma unroll
            for (int half = 0; half < 2; half++) {
                float ss = 0.f;
#pragma unroll
                for (int ni = 0; ni < 4; ni++) {
                    float v0 = acc[mi][ni][half*2], v1 = acc[mi][ni][half*2+1];
                    ss = fmaf(v0, v0, fmaf(v1, v1, ss));
                }
                ss += __shfl_xor_sync(0xffffffffu, ss, 1);
                ss += __shfl_xor_sync(0xffffffffu, ss, 2);
                if ((lane & 3) == 0) {
                    int rloc = wm*64 + mi*16 + r_lo + half*8;
                    red[rloc*4 + wn] = ss;
                }
            }
        }
        __syncthreads();
#pragma unroll
        for (int mi = 0; mi < 4; mi++)
#pragma unroll
            for (int half = 0; half < 2; half++) {
                int rloc = wm*64 + mi*16 + r_lo + half*8;
                float tot = red[rloc*4 + wn] + red[rloc*4 + (wn^1)];
                inv[mi][half] = 1.f / fmaxf(sqrtf(tot), 1e-12f);
            }
    }

#pragma unroll
    for (int mi = 0; mi < 4; mi++) {
#pragma unroll
        for (int ni = 0; ni < 4; ni++) {
#pragma unroll
            for (int half = 0; half < 2; half++) {
                int row = m0 + wm*64 + mi*16 + r_lo + half*8;
                int col = wn*32 + ni*8 + c_lo;       // 0..127 within tile
                float v0 = acc[mi][ni][half*2], v1 = acc[mi][ni][half*2 + 1];
                if (md == 2) { v0 *= inv[mi][half]; v1 *= inv[mi][half]; }
                if (md == 3) {
#pragma unroll
                    for (int e = 0; e < 2; e++) {
                        int cc = col + e;
                        float z = e ? v1 : v0;
                        if (cc < 16)      g_g [(size_t)row*HH + cc]        = sigmoidf_(z);
                        else if (cc < 32) g_f [(size_t)row*HH + cc - 16]   = sigmoidf_(z);
                        else if (cc < 96) g_g1[(size_t)row*HDIM + cc - 32] = z;
                    }
                } else {
                    *(float2*)(C + (size_t)row * DD + n0 + col) = make_float2(v0, v1);
                }
            }
        }
    }
}

// ---------------- gated delta-rule recurrence (3-slot, depth-2 prefetch) -----
__global__ __launch_bounds__(64) void recur_kernel() {
    const int blk = blockIdx.x;
    const int bh = blk >> 2, cg = blk & 3;
    const int b = bh >> 4, h = bh & 15;
    const int w = threadIdx.x >> 5, lane = threadIdx.x & 31;
    const int col = cg * 16 + w * 8 + (lane & 7);
    const int r0 = (lane >> 3) * 16;

    const size_t basev = (size_t)b * NNTOK * DD + h * HDIM;
    const float* kp = g_k + basev + r0;
    const float* qp = g_q + basev + r0;
    const float* vp = g_v + basev + col;
    float*       op = g_o + basev + col;
    const float* fp = g_f + (size_t)b * NNTOK * HH + h;
    const float* gp = g_g + (size_t)b * NNTOK * HH + h;

    float S[16];
#pragma unroll
    for (int i = 0; i < 16; i++) S[i] = 0.f;

    float4 kb[3][4], qb[3][4]; float vb[3], fb[3], cb[3];
    int tl = 0;
    auto prefetch = [&](int slot) {
#pragma unroll
        for (int i = 0; i < 4; i++) { kb[slot][i] = *(const float4*)(kp + 4*i); qb[slot][i] = *(const float4*)(qp + 4*i); }
        vb[slot] = *vp;
        float fv = *fp, gv = *gp;
        fb[slot] = fv;
        cb[slot] = -gv * fv * fv;          // off critical path
        if (tl < NNTOK - 1) { kp += DD; qp += DD; vp += DD; fp += HH; gp += HH; }
        tl++;
    };
    prefetch(0); prefetch(1);

    int t = 0;
    for (int it = 0; it < 683; it++) {
#pragma unroll
        for (int j = 0; j < 3; j++) {
            prefetch((j + 2) % 3);

            const float4* kf4 = kb[j];
            const float4* qf4 = qb[j];
            float kc[16], qc[16];
#pragma unroll
            for (int i = 0; i < 4; i++) {
                kc[4*i] = kf4[i].x; kc[4*i+1] = kf4[i].y; kc[4*i+2] = kf4[i].z; kc[4*i+3] = kf4[i].w;
                qc[4*i] = qf4[i].x; qc[4*i+1] = qf4[i].y; qc[4*i+2] = qf4[i].z; qc[4*i+3] = qf4[i].w;
            }
            const float vc = vb[j], fc = fb[j], cc0 = cb[j];

            float p0 = 0.f, p1 = 0.f, p2 = 0.f, p3 = 0.f;
#pragma unroll
            for (int i = 0; i < 4; i++) {
                p0 = fmaf(kc[i],    S[i],    p0);
                p1 = fmaf(kc[i+4],  S[i+4],  p1);
                p2 = fmaf(kc[i+8],  S[i+8],  p2);
                p3 = fmaf(kc[i+12], S[i+12], p3);
            }
            float d = (p0 + p1) + (p2 + p3);
            d += __shfl_xor_sync(0xffffffffu, d, 8);
            d += __shfl_xor_sync(0xffffffffu, d, 16);

            const float u = fmaf(cc0, d, vc);
            float o0 = 0.f, o1 = 0.f, o2 = 0.f, o3 = 0.f;
#pragma unroll
            for (int i = 0; i < 4; i++) {
                S[i]    = fmaf(fc, S[i],    kc[i]    * u); o0 = fmaf(qc[i],    S[i],    o0);
                S[i+4]  = fmaf(fc, S[i+4],  kc[i+4]  * u); o1 = fmaf(qc[i+4],  S[i+4],  o1);
                S[i+8]  = fmaf(fc, S[i+8],  kc[i+8]  * u); o2 = fmaf(qc[i+8],  S[i+8],  o2);
                S[i+12] = fmaf(fc, S[i+12], kc[i+12] * u); o3 = fmaf(qc[i+12], S[i+12], o3);
            }
            float o = (o0 + o1) + (o2 + o3);
            o += __shfl_xor_sync(0xffffffffu, o, 8);
            o += __shfl_xor_sync(0xffffffffu, o, 16);
            if (lane < 8 && t < NNTOK) op[(size_t)t * DD] = o;
            t++;
        }
    }
}

// -------- gate + LayerNorm -> bf16 hi/lo split directly ----------------------
__global__ __launch_bounds__(256) void gate_ln_kernel(const float* __restrict__ Wg2,
                                                      const float* __restrict__ nw) {
    __shared__ float g1s[8 * 64];
    __shared__ float rb[8 * 1024];
    const int row0 = blockIdx.x * 8;
    const int tid = threadIdx.x;
    for (int i = tid; i < 512; i += 256) g1s[i] = g_g1[(size_t)row0 * 64 + i];
    __syncthreads();
#pragma unroll
    for (int cs = 0; cs < 4; cs++) {
        const int c = tid + cs * 256;
        float a[8];
#pragma unroll
        for (int r = 0; r < 8; r++) a[r] = 0.f;
#pragma unroll 4
        for (int k = 0; k < 64; k++) {
            float wv = Wg2[(size_t)k * DD + c];
#pragma unroll
            for (int r = 0; r < 8; r++) a[r] = fmaf(g1s[r * 64 + k], wv, a[r]);
        }
#pragma unroll
        for (int r = 0; r < 8; r++)
            rb[r * 1024 + c] = g_o[(size_t)(row0 + r) * DD + c] * sigmoidf_(a[r]);
    }
    __syncthreads();
    const int wr = tid >> 5, ln = tid & 31;
    float s = 0.f, s2 = 0.f;
#pragma unroll 8
    for (int i = 0; i < 32; i++) {
        float v = rb[wr * 1024 + ln + 32 * i];
        s += v; s2 = fmaf(v, v, s2);
    }
#pragma unroll
    for (int o = 16; o; o >>= 1) {
        s  += __shfl_xor_sync(0xffffffffu, s,  o);
        s2 += __shfl_xor_sync(0xffffffffu, s2, o);
    }
    const float mu = s * (1.f / 1024.f);
    const float rstd = rsqrtf(s2 * (1.f / 1024.f) - mu * mu + 1e-5f);
#pragma unroll 8
    for (int i = 0; i < 32; i++) {
        int c = ln + 32 * i;
        float v = (rb[wr * 1024 + c] - mu) * rstd * nw[c];
        __nv_bfloat16 hi = __float2bfloat16(v);
        size_t idx = (size_t)(row0 + wr) * DD + c;
        g_nhi[idx] = hi;
        g_nlo[idx] = __float2bfloat16(v - __bfloat162float(hi));
    }
}

// -----------------------------------------------------------------------------
extern "C" void kernel_launch(void* const* d_in, const int* in_sizes, int n_in,
                              void* d_out, int out_size) {
    const float* x      = (const float*)d_in[0];
    const float* Wq     = (const float*)d_in[1];
    const float* Wk     = (const float*)d_in[2];
    const float* Wv     = (const float*)d_in[3];
    const float* Wgamma = (const float*)d_in[4];
    const float* Wf     = (const float*)d_in[5];
    const float* Wg1    = (const float*)d_in[6];
    const float* Wg2    = (const float*)d_in[7];
    const float* Wo     = (const float*)d_in[8];
    const float* norm_w = (const float*)d_in[9];
    float* out = (float*)d_out;

    cudaFuncSetAttribute(gemm_mma, cudaFuncAttributeMaxDynamicSharedMemorySize, GSMEM);

    __nv_bfloat16 *xh, *xl, *nh, *nl, *qh, *ql, *kh, *kl_, *vh, *vl, *oh, *ol, *sh, *sl;
    float *pq, *pk, *pv;
    cudaGetSymbolAddress((void**)&xh, g_xhi);  cudaGetSymbolAddress((void**)&xl, g_xlo);
    cudaGetSymbolAddress((void**)&nh, g_nhi);  cudaGetSymbolAddress((void**)&nl, g_nlo);
    cudaGetSymbolAddress((void**)&qh, g_wqhi); cudaGetSymbolAddress((void**)&ql, g_wqlo);
    cudaGetSymbolAddress((void**)&kh, g_wkhi); cudaGetSymbolAddress((void**)&kl_, g_wklo);
    cudaGetSymbolAddress((void**)&vh, g_wvhi); cudaGetSymbolAddress((void**)&vl, g_wvlo);
    cudaGetSymbolAddress((void**)&oh, g_wohi); cudaGetSymbolAddress((void**)&ol, g_wolo);
    cudaGetSymbolAddress((void**)&sh, g_wshi); cudaGetSymbolAddress((void**)&sl, g_wslo);
    cudaGetSymbolAddress((void**)&pq, g_q);    cudaGetSymbolAddress((void**)&pk, g_k);
    cudaGetSymbolAddress((void**)&pv, g_v);

    prep_kernel<<<16384 + 4096 + 128, 256>>>(x, Wq, Wk, Wv, Wo, Wgamma, Wf, Wg1);  // 0

    gemm_mma<<<dim3(9, 32), 256, GSMEM>>>(xh, xl, qh, ql, sh, sl, pq, 1);   // 1: q + small scatter
    gemm_mma<<<dim3(8, 32), 256, GSMEM>>>(xh, xl, kh, kl_, sh, sl, pk, 2);  // 2: k + silu + l2norm
    gemm_mma<<<dim3(8, 32), 256, GSMEM>>>(xh, xl, vh, vl, sh, sl, pv, 1);   // 3: v

    recur_kernel<<<128, 64>>>();                                            // 4
    gate_ln_kernel<<<BN/8, 256>>>(Wg2, norm_w);                             // 5 <- ncu capture
    gemm_mma<<<dim3(8, 32), 256, GSMEM>>>(nh, nl, oh, ol, sh, sl, out, 0);  // 6
}

// round 7
// speedup vs baseline: 1.7265x; 1.7265x over previous
#include <cuda_runtime.h>
#include <cuda_bf16.h>
#include <math.h>
#include <stdint.h>

#define BB 2
#define NNTOK 2048
#define DD 1024
#define HH 16
#define HDIM 64
#define BN (BB*NNTOK)
#define RT 32   /* recurrence smem tile (timesteps) */

// ---------------- scratch (device globals) ----------------------------------
__device__ __nv_bfloat16 g_xhi[BN*DD], g_xlo[BN*DD];
__device__ __nv_bfloat16 g_nhi[BN*DD], g_nlo[BN*DD];
__device__ __nv_bfloat16 g_wqhi[DD*DD], g_wqlo[DD*DD];
__device__ __nv_bfloat16 g_wkhi[DD*DD], g_wklo[DD*DD];
__device__ __nv_bfloat16 g_wvhi[DD*DD], g_wvlo[DD*DD];
__device__ __nv_bfloat16 g_wohi[DD*DD], g_wolo[DD*DD];
__device__ __nv_bfloat16 g_wshi[128*DD], g_wslo[128*DD];
__device__ float g_q [BN*DD];
__device__ float g_k [BN*DD];
__device__ float g_v [BN*DD];
__device__ float g_o [BN*DD];
__device__ float g_f [BN*HH];
__device__ float g_g [BN*HH];
__device__ float g_g1[BN*HDIM];

__device__ __forceinline__ float sigmoidf_(float x) { return 1.f / (1.f + expf(-x)); }

__device__ __forceinline__ uint32_t s2u(const void* p) {
    uint32_t a;
    asm("{ .reg .u64 t; cvta.to.shared.u64 t, %1; cvt.u32.u64 %0, t; }" : "=r"(a) : "l"(p));
    return a;
}
__device__ __forceinline__ void cp16(uint32_t dst, const void* src) {
    asm volatile("cp.async.cg.shared.global [%0], [%1], 16;" :: "r"(dst), "l"(src) : "memory");
}
__device__ __forceinline__ void cp4(uint32_t dst, const void* src) {
    asm volatile("cp.async.ca.shared.global [%0], [%1], 4;" :: "r"(dst), "l"(src) : "memory");
}
__device__ __forceinline__ void ldm4(uint32_t* r, uint32_t addr) {
    asm volatile("ldmatrix.sync.aligned.m8n8.x4.shared.b16 {%0,%1,%2,%3}, [%4];"
        : "=r"(r[0]), "=r"(r[1]), "=r"(r[2]), "=r"(r[3]) : "r"(addr));
}
__device__ __forceinline__ void mma16816(float* d, const uint32_t* a, const uint32_t* b) {
    asm volatile("mma.sync.aligned.m16n8k16.row.col.f32.bf16.bf16.f32 "
        "{%0,%1,%2,%3}, {%4,%5,%6,%7}, {%8,%9}, {%0,%1,%2,%3};"
        : "+f"(d[0]), "+f"(d[1]), "+f"(d[2]), "+f"(d[3])
        : "r"(a[0]), "r"(a[1]), "r"(a[2]), "r"(a[3]), "r"(b[0]), "r"(b[1]));
}

// ---------------- merged prep: conv_a + 4x conv_wT + conv_small ---------------
__global__ __launch_bounds__(256) void prep_kernel(
    const float* __restrict__ x,
    const float* __restrict__ Wq, const float* __restrict__ Wk,
    const float* __restrict__ Wv, const float* __restrict__ Wo,
    const float* __restrict__ Wg, const float* __restrict__ Wf,
    const float* __restrict__ Wg1)
{
    __shared__ float ts[32][33];
    const int bid = blockIdx.x, tid = threadIdx.x;
    if (bid < 16384) {
        int i = bid * 256 + tid;
        float v = x[i];
        __nv_bfloat16 h = __float2bfloat16(v);
        g_xhi[i] = h;
        g_xlo[i] = __float2bfloat16(v - __bfloat162float(h));
    } else if (bid < 16384 + 4096) {
        int t = bid - 16384;
        int z = t >> 10, rem = t & 1023;
        int bx = rem & 31, by = rem >> 5;
        const float* W; __nv_bfloat16 *hi, *lo;
        switch (z) {
            case 0:  W = Wq; hi = g_wqhi; lo = g_wqlo; break;
            case 1:  W = Wk; hi = g_wkhi; lo = g_wklo; break;
            case 2:  W = Wv; hi = g_wvhi; lo = g_wvlo; break;
            default: W = Wo; hi = g_wohi; lo = g_wolo; break;
        }
        const int r = tid >> 5, c = tid & 31;
#pragma unroll
        for (int i = 0; i < 4; i++)
            ts[r + 8*i][c] = W[(size_t)(by*32 + r + 8*i) * DD + bx*32 + c];
        __syncthreads();
#pragma unroll
        for (int i = 0; i < 4; i++) {
            int n = bx*32 + r + 8*i, k = by*32 + c;
            float v = ts[c][r + 8*i];
            __nv_bfloat16 h = __float2bfloat16(v);
            hi[(size_t)n*DD + k] = h;
            lo[(size_t)n*DD + k] = __float2bfloat16(v - __bfloat162float(h));
        }
    } else {
        int n = bid - (16384 + 4096);
        for (int k = tid; k < DD; k += 256) {
            float v = (n < 16) ? Wg[(size_t)k*16 + n] : (n < 32) ? Wf[(size_t)k*16 + n - 16]
                    : (n < 96) ? Wg1[(size_t)k*64 + n - 32] : 0.f;
            __nv_bfloat16 h = __float2bfloat16(v);
            g_wshi[(size_t)n*DD + k] = h;
            g_wslo[(size_t)n*DD + k] = __float2bfloat16(v - __bfloat162float(h));
        }
    }
}

// ---------------- bf16 split GEMM via mma.sync + ldmatrix --------------------
#define PITCH 80
#define ABUF (128*PITCH)
#define STG (2*ABUF)
#define GSMEM (4*STG)
__global__ __launch_bounds__(256, 2) void gemm_mma(
    const __nv_bfloat16* __restrict__ Ahi, const __nv_bfloat16* __restrict__ Alo,
    const __nv_bfloat16* __restrict__ Bhi, const __nv_bfloat16* __restrict__ Blo,
    const __nv_bfloat16* __restrict__ B2hi, const __nv_bfloat16* __restrict__ B2lo,
    float* __restrict__ C, int mode)
{
    extern __shared__ __align__(16) char sm[];
    const uint32_t sb = s2u(sm);
    const int tid = threadIdx.x, wid = tid >> 5, lane = tid & 31;
    const int wm = wid >> 2, wn = wid & 3;
    const int tn = blockIdx.x;
    const int m0 = blockIdx.y * 128;
    int md = mode, n0 = tn * 128;
    if (tn == 8) { Bhi = B2hi; Blo = B2lo; md = 3; n0 = 0; }

    float acc[4][4][4];
#pragma unroll
    for (int i = 0; i < 4; i++)
#pragma unroll
        for (int j = 0; j < 4; j++)
#pragma unroll
            for (int l = 0; l < 4; l++) acc[i][j][l] = 0.f;

    auto load_chunk = [&](int kf) {
        const int seg = kf >> 5;
        const __nv_bfloat16* Aa = (seg == 1) ? Alo : Ahi;
        const __nv_bfloat16* Ba = (seg == 2) ? Blo : Bhi;
        const int kl = (kf & 31) * 32;
        const uint32_t base = sb + (uint32_t)(kf & 3) * STG;
#pragma unroll
        for (int i = 0; i < 2; i++) {
            int idx = tid + i * 256;
            int row = idx >> 2, q = idx & 3;
            cp16(base + row * PITCH + q * 16, Aa + (size_t)(m0 + row) * DD + kl + q * 8);
            cp16(base + ABUF + row * PITCH + q * 16, Ba + (size_t)(n0 + row) * DD + kl + q * 8);
        }
        asm volatile("cp.async.commit_group;" ::: "memory");
    };

    load_chunk(0); load_chunk(1); load_chunk(2);

    const int la = lane & 15, lb8 = (lane >> 4) * 16;
    const int rb_row = ((lane >> 4) & 1) * 8 + (lane & 7);
    const int rb_col = ((lane >> 3) & 1) * 16;
    uint32_t offa[4], offb[2];
#pragma unroll
    for (int mi = 0; mi < 4; mi++) offa[mi] = (uint32_t)((wm*64 + mi*16 + la) * PITCH + lb8);
#pragma unroll
    for (int nj = 0; nj < 2; nj++) offb[nj] = (uint32_t)((wn*32 + nj*16 + rb_row) * PITCH + rb_col);

    for (int kc = 0; kc < 96; kc++) {
        asm volatile("cp.async.wait_group 2;" ::: "memory");
        __syncthreads();

        const uint32_t As = sb + (uint32_t)(kc & 3) * STG;
        const uint32_t Bs = As + ABUF;
        uint32_t a[2][4][4], b[2][4][2];
#pragma unroll
        for (int ks = 0; ks < 2; ks++) {
#pragma unroll
            for (int mi = 0; mi < 4; mi++) ldm4(a[ks][mi], As + offa[mi] + ks*32);
#pragma unroll
            for (int nj = 0; nj < 2; nj++) {
                uint32_t t[4];
                ldm4(t, Bs + offb[nj] + ks*32);
                b[ks][nj*2][0] = t[0]; b[ks][nj*2][1] = t[1];
                b[ks][nj*2+1][0] = t[2]; b[ks][nj*2+1][1] = t[3];
            }
        }
        if (kc + 3 < 96) load_chunk(kc + 3);
        else asm volatile("cp.async.commit_group;" ::: "memory");
#pragma unroll
        for (int ks = 0; ks < 2; ks++)
#pragma unroll
            for (int mi = 0; mi < 4; mi++)
#pragma unroll
                for (int ni = 0; ni < 4; ni++)
                    mma16816(acc[mi][ni], a[ks][mi], b[ks][ni]);
    }

    const int r_lo = lane >> 2, c_lo = (lane & 3) * 2;

    if (md == 1 || md == 2) {
#pragma unroll
        for (int mi = 0; mi < 4; mi++)
#pragma unroll
            for (int ni = 0; ni < 4; ni++)
#pragma unroll
                for (int l = 0; l < 4; l++) {
                    float z = acc[mi][ni][l];
                    acc[mi][ni][l] = z * sigmoidf_(z);
                }
    }

    float inv[4][2];
#pragma unroll
    for (int mi = 0; mi < 4; mi++) { inv[mi][0] = 1.f; inv[mi][1] = 1.f; }

    if (md == 2) {
        __syncthreads();
        float* red = (float*)sm;
#pragma unroll
        for (int mi = 0; mi < 4; mi++) {
#pragma unroll
            for (int half = 0; half < 2; half++) {
                float ss = 0.f;
#pragma unroll
                for (int ni = 0; ni < 4; ni++) {
                    float v0 = acc[mi][ni][half*2], v1 = acc[mi][ni][half*2+1];
                    ss = fmaf(v0, v0, fmaf(v1, v1, ss));
                }
                ss += __shfl_xor_sync(0xffffffffu, ss, 1);
                ss += __shfl_xor_sync(0xffffffffu, ss, 2);
                if ((lane & 3) == 0) {
                    int rloc = wm*64 + mi*16 + r_lo + half*8;
                    red[rloc*4 + wn] = ss;
                }
            }
        }
        __syncthreads();
#pragma unroll
        for (int mi = 0; mi < 4; mi++)
#pragma unroll
            for (int half = 0; half < 2; half++) {
                int rloc = wm*64 + mi*16 + r_lo + half*8;
                float tot = red[rloc*4 + wn] + red[rloc*4 + (wn^1)];
                inv[mi][half] = 1.f / fmaxf(sqrtf(tot), 1e-12f);
            }
    }

#pragma unroll
    for (int mi = 0; mi < 4; mi++) {
#pragma unroll
        for (int ni = 0; ni < 4; ni++) {
#pragma unroll
            for (int half = 0; half < 2; half++) {
                int row = m0 + wm*64 + mi*16 + r_lo + half*8;
                int col = wn*32 + ni*8 + c_lo;
                float v0 = acc[mi][ni][half*2], v1 = acc[mi][ni][half*2 + 1];
                if (md == 2) { v0 *= inv[mi][half]; v1 *= inv[mi][half]; }
                if (md == 3) {
#pragma unroll
                    for (int e = 0; e < 2; e++) {
                        int cc = col + e;
                        float z = e ? v1 : v0;
                        if (cc < 16)      g_g [(size_t)row*HH + cc]        = sigmoidf_(z);
                        else if (cc < 32) g_f [(size_t)row*HH + cc - 16]   = sigmoidf_(z);
                        else if (cc < 96) g_g1[(size_t)row*HDIM + cc - 32] = z;
                    }
                } else {
                    *(float2*)(C + (size_t)row * DD + n0 + col) = make_float2(v0, v1);
                }
            }
        }
    }
}

// ---------------- gated delta-rule recurrence: smem-staged -------------------
// 64 blocks = (b,h) x 2 col-halves. 128 threads = 4 warps x 8 cols.
// lane: col = ch*32 + w*8 + (lane&7), rows r0=(lane>>3)*16 .. +16.
__global__ __launch_bounds__(128) void recur_kernel() {
    __shared__ float ks[2][RT][64], qs[2][RT][64], vs[2][RT][32];
    __shared__ float fs[2][RT], gs_[2][RT];

    const int blk = blockIdx.x;
    const int bh = blk >> 1, ch = blk & 1;
    const int b = bh >> 4, h = bh & 15;
    const int tid = threadIdx.x;
    const int w = tid >> 5, lane = tid & 31;
    const int col = ch*32 + w*8 + (lane & 7);
    const int r0 = (lane >> 3) * 16;

    const size_t basev = (size_t)b * NNTOK * DD + h * HDIM;
    const size_t basef = (size_t)b * NNTOK * HH + h;

    auto stage = [&](int tile, int buf) {
        const int t0 = tile * RT;
#pragma unroll
        for (int p = 0; p < 4; p++) {
            int idx = tid + p * 128;
            int r = idx >> 4, i = (idx & 15) * 4;
            cp16(s2u(&ks[buf][r][i]), g_k + basev + (size_t)(t0 + r) * DD + i);
            cp16(s2u(&qs[buf][r][i]), g_q + basev + (size_t)(t0 + r) * DD + i);
        }
#pragma unroll
        for (int p = 0; p < 2; p++) {
            int idx = tid + p * 128;
            int r = idx >> 3, i = (idx & 7) * 4;
            cp16(s2u(&vs[buf][r][i]), g_v + basev + (size_t)(t0 + r) * DD + ch*32 + i);
        }
        if (tid < RT)           cp4(s2u(&fs[buf][tid]),       g_f + basef + (size_t)(t0 + tid) * HH);
        else if (tid < 2*RT)    cp4(s2u(&gs_[buf][tid - RT]), g_g + basef + (size_t)(t0 + tid - RT) * HH);
        asm volatile("cp.async.commit_group;" ::: "memory");
    };

    float S[16];
#pragma unroll
    for (int i = 0; i < 16; i++) S[i] = 0.f;

    auto loadkq = [&](int buf, int tt, float* kc, float* qc) {
#pragma unroll
        for (int i = 0; i < 4; i++) {
            float4 kv = *(const float4*)&ks[buf][tt][r0 + 4*i];
            float4 qv = *(const float4*)&qs[buf][tt][r0 + 4*i];
            kc[4*i] = kv.x; kc[4*i+1] = kv.y; kc[4*i+2] = kv.z; kc[4*i+3] = kv.w;
            qc[4*i] = qv.x; qc[4*i+1] = qv.y; qc[4*i+2] = qv.z; qc[4*i+3] = qv.w;
        }
    };

    auto dostep = [&](int buf, int t, int tt, const float* kc, const float* qc) {
        const float vc = vs[buf][tt][w*8 + (lane & 7)];
        const float fc = fs[buf][tt];
        const float gv = gs_[buf][tt];
        const float cc0 = -gv * fc * fc;

        float p0 = 0.f, p1 = 0.f, p2 = 0.f, p3 = 0.f;
#pragma unroll
        for (int i = 0; i < 4; i++) {
            p0 = fmaf(kc[i],    S[i],    p0);
            p1 = fmaf(kc[i+4],  S[i+4],  p1);
            p2 = fmaf(kc[i+8],  S[i+8],  p2);
            p3 = fmaf(kc[i+12], S[i+12], p3);
        }
        float d = (p0 + p1) + (p2 + p3);
        d += __shfl_xor_sync(0xffffffffu, d, 8);
        d += __shfl_xor_sync(0xffffffffu, d, 16);

        const float u = fmaf(cc0, d, vc);
        float o0 = 0.f, o1 = 0.f, o2 = 0.f, o3 = 0.f;
#pragma unroll
        for (int i = 0; i < 4; i++) {
            S[i]    = fmaf(fc, S[i],    kc[i]    * u); o0 = fmaf(qc[i],    S[i],    o0);
            S[i+4]  = fmaf(fc, S[i+4],  kc[i+4]  * u); o1 = fmaf(qc[i+4],  S[i+4],  o1);
            S[i+8]  = fmaf(fc, S[i+8],  kc[i+8]  * u); o2 = fmaf(qc[i+8],  S[i+8],  o2);
            S[i+12] = fmaf(fc, S[i+12], kc[i+12] * u); o3 = fmaf(qc[i+12], S[i+12], o3);
        }
        float o = (o0 + o1) + (o2 + o3);
        o += __shfl_xor_sync(0xffffffffu, o, 8);
        o += __shfl_xor_sync(0xffffffffu, o, 16);
        if (lane < 8) g_o[basev + (size_t)t * DD + col] = o;
    };

    stage(0, 0);
    const int NT = NNTOK / RT;   // 64 tiles
    for (int tile = 0; tile < NT; tile++) {
        const int buf = tile & 1;
        __syncthreads();                     // everyone done computing buf^1
        if (tile + 1 < NT) {
            stage(tile + 1, buf ^ 1);
            asm volatile("cp.async.wait_group 1;" ::: "memory");
        } else {
            asm volatile("cp.async.wait_group 0;" ::: "memory");
        }
        __syncthreads();                     // tile data visible

        const int t0 = tile * RT;
        float ka[16], qa[16], kb[16], qb[16];
        loadkq(buf, 0, ka, qa);
        for (int tt = 0; tt < RT; tt += 2) {
            if (tt + 1 < RT) loadkq(buf, tt + 1, kb, qb);
            dostep(buf, t0 + tt, tt, ka, qa);
            if (tt + 2 < RT) loadkq(buf, tt + 2, ka, qa);
            dostep(buf, t0 + tt + 1, tt + 1, kb, qb);
        }
    }
}

// -------- gate + LayerNorm -> bf16 hi/lo split directly ----------------------
__global__ __launch_bounds__(256) void gate_ln_kernel(const float* __restrict__ Wg2,
                                                      const float* __restrict__ nw) {
    __shared__ float g1s[8 * 64];
    __shared__ float rb[8 * 1024];
    const int row0 = blockIdx.x * 8;
    const int tid = threadIdx.x;
    for (int i = tid; i < 512; i += 256) g1s[i] = g_g1[(size_t)row0 * 64 + i];
    __syncthreads();
#pragma unroll
    for (int cs = 0; cs < 4; cs++) {
        const int c = tid + cs * 256;
        float a[8];
#pragma unroll
        for (int r = 0; r < 8; r++) a[r] = 0.f;
#pragma unroll 4
        for (int k = 0; k < 64; k++) {
            float wv = Wg2[(size_t)k * DD + c];
#pragma unroll
            for (int r = 0; r < 8; r++) a[r] = fmaf(g1s[r * 64 + k], wv, a[r]);
        }
#pragma unroll
        for (int r = 0; r < 8; r++)
            rb[r * 1024 + c] = g_o[(size_t)(row0 + r) * DD + c] * sigmoidf_(a[r]);
    }
    __syncthreads();
    const int wr = tid >> 5, ln = tid & 31;
    float s = 0.f, s2 = 0.f;
#pragma unroll 8
    for (int i = 0; i < 32; i++) {
        float v = rb[wr * 1024 + ln + 32 * i];
        s += v; s2 = fmaf(v, v, s2);
    }
#pragma unroll
    for (int o = 16; o; o >>= 1) {
        s  += __shfl_xor_sync(0xffffffffu, s,  o);
        s2 += __shfl_xor_sync(0xffffffffu, s2, o);
    }
    const float mu = s * (1.f / 1024.f);
    const float rstd = rsqrtf(s2 * (1.f / 1024.f) - mu * mu + 1e-5f);
#pragma unroll 8
    for (int i = 0; i < 32; i++) {
        int c = ln + 32 * i;
        float v = (rb[wr * 1024 + c] - mu) * rstd * nw[c];
        __nv_bfloat16 hi = __float2bfloat16(v);
        size_t idx = (size_t)(row0 + wr) * DD + c;
        g_nhi[idx] = hi;
        g_nlo[idx] = __float2bfloat16(v - __bfloat162float(hi));
    }
}

// -----------------------------------------------------------------------------
extern "C" void kernel_launch(void* const* d_in, const int* in_sizes, int n_in,
                              void* d_out, int out_size) {
    const float* x      = (const float*)d_in[0];
    const float* Wq     = (const float*)d_in[1];
    const float* Wk     = (const float*)d_in[2];
    const float* Wv     = (const float*)d_in[3];
    const float* Wgamma = (const float*)d_in[4];
    const float* Wf     = (const float*)d_in[5];
    const float* Wg1    = (const float*)d_in[6];
    const float* Wg2    = (const float*)d_in[7];
    const float* Wo     = (const float*)d_in[8];
    const float* norm_w = (const float*)d_in[9];
    float* out = (float*)d_out;

    cudaFuncSetAttribute(gemm_mma, cudaFuncAttributeMaxDynamicSharedMemorySize, GSMEM);

    __nv_bfloat16 *xh, *xl, *nh, *nl, *qh, *ql, *kh, *kl_, *vh, *vl, *oh, *ol, *sh, *sl;
    float *pq, *pk, *pv;
    cudaGetSymbolAddress((void**)&xh, g_xhi);  cudaGetSymbolAddress((void**)&xl, g_xlo);
    cudaGetSymbolAddress((void**)&nh, g_nhi);  cudaGetSymbolAddress((void**)&nl, g_nlo);
    cudaGetSymbolAddress((void**)&qh, g_wqhi); cudaGetSymbolAddress((void**)&ql, g_wqlo);
    cudaGetSymbolAddress((void**)&kh, g_wkhi); cudaGetSymbolAddress((void**)&kl_, g_wklo);
    cudaGetSymbolAddress((void**)&vh, g_wvhi); cudaGetSymbolAddress((void**)&vl, g_wvlo);
    cudaGetSymbolAddress((void**)&oh, g_wohi); cudaGetSymbolAddress((void**)&ol, g_wolo);
    cudaGetSymbolAddress((void**)&sh, g_wshi); cudaGetSymbolAddress((void**)&sl, g_wslo);
    cudaGetSymbolAddress((void**)&pq, g_q);    cudaGetSymbolAddress((void**)&pk, g_k);
    cudaGetSymbolAddress((void**)&pv, g_v);

    prep_kernel<<<16384 + 4096 + 128, 256>>>(x, Wq, Wk, Wv, Wo, Wgamma, Wf, Wg1);

    gemm_mma<<<dim3(9, 32), 256, GSMEM>>>(xh, xl, qh, ql, sh, sl, pq, 1);   // q + small scatter
    gemm_mma<<<dim3(8, 32), 256, GSMEM>>>(xh, xl, kh, kl_, sh, sl, pk, 2);  // k + silu + l2norm
    gemm_mma<<<dim3(8, 32), 256, GSMEM>>>(xh, xl, vh, vl, sh, sl, pv, 1);   // v

    recur_kernel<<<64, 128>>>();
    gate_ln_kernel<<<BN/8, 256>>>(Wg2, norm_w);
    gemm_mma<<<dim3(8, 32), 256, GSMEM>>>(nh, nl, oh, ol, sh, sl, out, 0);
}

// round 8
// speedup vs baseline: 1.8080x; 1.0472x over previous
#include <cuda_runtime.h>
#include <cuda_bf16.h>
#include <math.h>
#include <stdint.h>

#define BB 2
#define NNTOK 2048
#define DD 1024
#define HH 16
#define HDIM 64
#define BN (BB*NNTOK)
#define RT 32

// ---------------- scratch (device globals) ----------------------------------
__device__ __nv_bfloat16 g_xhi[BN*DD], g_xlo[BN*DD];
__device__ __nv_bfloat16 g_nhi[BN*DD], g_nlo[BN*DD];
__device__ __nv_bfloat16 g_wqhi[DD*DD], g_wqlo[DD*DD];
__device__ __nv_bfloat16 g_wkhi[DD*DD], g_wklo[DD*DD];
__device__ __nv_bfloat16 g_wvhi[DD*DD], g_wvlo[DD*DD];
__device__ __nv_bfloat16 g_wohi[DD*DD], g_wolo[DD*DD];
__device__ __nv_bfloat16 g_wshi[128*DD], g_wslo[128*DD];
__device__ float g_q [BN*DD];
__device__ float g_k [BN*DD];
__device__ float g_v [BN*DD];
__device__ float g_o [BN*DD];
__device__ float g_f [BN*HH];
__device__ float g_g [BN*HH];
__device__ float g_g1[BN*HDIM];

__device__ __forceinline__ float sigmoidf_(float x) { return 1.f / (1.f + expf(-x)); }

__device__ __forceinline__ uint32_t s2u(const void* p) {
    uint32_t a;
    asm("{ .reg .u64 t; cvta.to.shared.u64 t, %1; cvt.u32.u64 %0, t; }" : "=r"(a) : "l"(p));
    return a;
}
__device__ __forceinline__ void cp16(uint32_t dst, const void* src) {
    asm volatile("cp.async.cg.shared.global [%0], [%1], 16;" :: "r"(dst), "l"(src) : "memory");
}
__device__ __forceinline__ void cp4(uint32_t dst, const void* src) {
    asm volatile("cp.async.ca.shared.global [%0], [%1], 4;" :: "r"(dst), "l"(src) : "memory");
}
__device__ __forceinline__ void ldm4(uint32_t* r, uint32_t addr) {
    asm volatile("ldmatrix.sync.aligned.m8n8.x4.shared.b16 {%0,%1,%2,%3}, [%4];"
        : "=r"(r[0]), "=r"(r[1]), "=r"(r[2]), "=r"(r[3]) : "r"(addr));
}
__device__ __forceinline__ void mma16816(float* d, const uint32_t* a, const uint32_t* b) {
    asm volatile("mma.sync.aligned.m16n8k16.row.col.f32.bf16.bf16.f32 "
        "{%0,%1,%2,%3}, {%4,%5,%6,%7}, {%8,%9}, {%0,%1,%2,%3};"
        : "+f"(d[0]), "+f"(d[1]), "+f"(d[2]), "+f"(d[3])
        : "r"(a[0]), "r"(a[1]), "r"(a[2]), "r"(a[3]), "r"(b[0]), "r"(b[1]));
}

// ---------------- merged prep ------------------------------------------------
__global__ __launch_bounds__(256) void prep_kernel(
    const float* __restrict__ x,
    const float* __restrict__ Wq, const float* __restrict__ Wk,
    const float* __restrict__ Wv, const float* __restrict__ Wo,
    const float* __restrict__ Wg, const float* __restrict__ Wf,
    const float* __restrict__ Wg1)
{
    __shared__ float ts[32][33];
    const int bid = blockIdx.x, tid = threadIdx.x;
    if (bid < 16384) {
        int i = bid * 256 + tid;
        float v = x[i];
        __nv_bfloat16 h = __float2bfloat16(v);
        g_xhi[i] = h;
        g_xlo[i] = __float2bfloat16(v - __bfloat162float(h));
    } else if (bid < 16384 + 4096) {
        int t = bid - 16384;
        int z = t >> 10, rem = t & 1023;
        int bx = rem & 31, by = rem >> 5;
        const float* W; __nv_bfloat16 *hi, *lo;
        switch (z) {
            case 0:  W = Wq; hi = g_wqhi; lo = g_wqlo; break;
            case 1:  W = Wk; hi = g_wkhi; lo = g_wklo; break;
            case 2:  W = Wv; hi = g_wvhi; lo = g_wvlo; break;
            default: W = Wo; hi = g_wohi; lo = g_wolo; break;
        }
        const int r = tid >> 5, c = tid & 31;
#pragma unroll
        for (int i = 0; i < 4; i++)
            ts[r + 8*i][c] = W[(size_t)(by*32 + r + 8*i) * DD + bx*32 + c];
        __syncthreads();
#pragma unroll
        for (int i = 0; i < 4; i++) {
            int n = bx*32 + r + 8*i, k = by*32 + c;
            float v = ts[c][r + 8*i];
            __nv_bfloat16 h = __float2bfloat16(v);
            hi[(size_t)n*DD + k] = h;
            lo[(size_t)n*DD + k] = __float2bfloat16(v - __bfloat162float(h));
        }
    } else {
        int n = bid - (16384 + 4096);
        for (int k = tid; k < DD; k += 256) {
            float v = (n < 16) ? Wg[(size_t)k*16 + n] : (n < 32) ? Wf[(size_t)k*16 + n - 16]
                    : (n < 96) ? Wg1[(size_t)k*64 + n - 32] : 0.f;
            __nv_bfloat16 h = __float2bfloat16(v);
            g_wshi[(size_t)n*DD + k] = h;
            g_wslo[(size_t)n*DD + k] = __float2bfloat16(v - __bfloat162float(h));
        }
    }
}

// ---------------- bf16 split GEMM core ---------------------------------------
#define PITCH 80
#define ABUF (128*PITCH)
#define STG (2*ABUF)
#define GSMEM (4*STG)
__device__ __forceinline__ void gemm_core(
    const __nv_bfloat16* __restrict__ Ahi, const __nv_bfloat16* __restrict__ Alo,
    const __nv_bfloat16* __restrict__ Bhi, const __nv_bfloat16* __restrict__ Blo,
    float* __restrict__ C, int md, int m0, int n0)
{
    extern __shared__ __align__(16) char sm[];
    const uint32_t sb = s2u(sm);
    const int tid = threadIdx.x, wid = tid >> 5, lane = tid & 31;
    const int wm = wid >> 2, wn = wid & 3;

    float acc[4][4][4];
#pragma unroll
    for (int i = 0; i < 4; i++)
#pragma unroll
        for (int j = 0; j < 4; j++)
#pragma unroll
            for (int l = 0; l < 4; l++) acc[i][j][l] = 0.f;

    auto load_chunk = [&](int kf) {
        const int seg = kf >> 5;
        const __nv_bfloat16* Aa = (seg == 1) ? Alo : Ahi;
        const __nv_bfloat16* Ba = (seg == 2) ? Blo : Bhi;
        const int kl = (kf & 31) * 32;
        const uint32_t base = sb + (uint32_t)(kf & 3) * STG;
#pragma unroll
        for (int i = 0; i < 2; i++) {
            int idx = tid + i * 256;
            int row = idx >> 2, q = idx & 3;
            cp16(base + row * PITCH + q * 16, Aa + (size_t)(m0 + row) * DD + kl + q * 8);
            cp16(base + ABUF + row * PITCH + q * 16, Ba + (size_t)(n0 + row) * DD + kl + q * 8);
        }
        asm volatile("cp.async.commit_group;" ::: "memory");
    };

    load_chunk(0); load_chunk(1); load_chunk(2);

    const int la = lane & 15, lb8 = (lane >> 4) * 16;
    const int rb_row = ((lane >> 4) & 1) * 8 + (lane & 7);
    const int rb_col = ((lane >> 3) & 1) * 16;
    uint32_t offa[4], offb[2];
#pragma unroll
    for (int mi = 0; mi < 4; mi++) offa[mi] = (uint32_t)((wm*64 + mi*16 + la) * PITCH + lb8);
#pragma unroll
    for (int nj = 0; nj < 2; nj++) offb[nj] = (uint32_t)((wn*32 + nj*16 + rb_row) * PITCH + rb_col);

    for (int kc = 0; kc < 96; kc++) {
        asm volatile("cp.async.wait_group 2;" ::: "memory");
        __syncthreads();

        const uint32_t As = sb + (uint32_t)(kc & 3) * STG;
        const uint32_t Bs = As + ABUF;
        uint32_t a[2][4][4], b[2][4][2];
#pragma unroll
        for (int ks = 0; ks < 2; ks++) {
#pragma unroll
            for (int mi = 0; mi < 4; mi++) ldm4(a[ks][mi], As + offa[mi] + ks*32);
#pragma unroll
            for (int nj = 0; nj < 2; nj++) {
                uint32_t t[4];
                ldm4(t, Bs + offb[nj] + ks*32);
                b[ks][nj*2][0] = t[0]; b[ks][nj*2][1] = t[1];
                b[ks][nj*2+1][0] = t[2]; b[ks][nj*2+1][1] = t[3];
            }
        }
        if (kc + 3 < 96) load_chunk(kc + 3);
        else asm volatile("cp.async.commit_group;" ::: "memory");
#pragma unroll
        for (int ks = 0; ks < 2; ks++)
#pragma unroll
            for (int mi = 0; mi < 4; mi++)
#pragma unroll
                for (int ni = 0; ni < 4; ni++)
                    mma16816(acc[mi][ni], a[ks][mi], b[ks][ni]);
    }

    const int r_lo = lane >> 2, c_lo = (lane & 3) * 2;

    if (md == 1 || md == 2) {
#pragma unroll
        for (int mi = 0; mi < 4; mi++)
#pragma unroll
            for (int ni = 0; ni < 4; ni++)
#pragma unroll
                for (int l = 0; l < 4; l++) {
                    float z = acc[mi][ni][l];
                    acc[mi][ni][l] = z * sigmoidf_(z);
                }
    }

    float inv[4][2];
#pragma unroll
    for (int mi = 0; mi < 4; mi++) { inv[mi][0] = 1.f; inv[mi][1] = 1.f; }

    if (md == 2) {
        __syncthreads();
        float* red = (float*)sm;
#pragma unroll
        for (int mi = 0; mi < 4; mi++) {
#pragma unroll
            for (int half = 0; half < 2; half++) {
                float ss = 0.f;
#pragma unroll
                for (int ni = 0; ni < 4; ni++) {
                    float v0 = acc[mi][ni][half*2], v1 = acc[mi][ni][half*2+1];
                    ss = fmaf(v0, v0, fmaf(v1, v1, ss));
                }
                ss += __shfl_xor_sync(0xffffffffu, ss, 1);
                ss += __shfl_xor_sync(0xffffffffu, ss, 2);
                if ((lane & 3) == 0) {
                    int rloc = wm*64 + mi*16 + r_lo + half*8;
                    red[rloc*4 + wn] = ss;
                }
            }
        }
        __syncthreads();
#pragma unroll
        for (int mi = 0; mi < 4; mi++)
#pragma unroll
            for (int half = 0; half < 2; half++) {
                int rloc = wm*64 + mi*16 + r_lo + half*8;
                float tot = red[rloc*4 + wn] + red[rloc*4 + (wn^1)];
                inv[mi][half] = 1.f / fmaxf(sqrtf(tot), 1e-12f);
            }
    }

#pragma unroll
    for (int mi = 0; mi < 4; mi++) {
#pragma unroll
        for (int ni = 0; ni < 4; ni++) {
#pragma unroll
            for (int half = 0; half < 2; half++) {
                int row = m0 + wm*64 + mi*16 + r_lo + half*8;
                int col = wn*32 + ni*8 + c_lo;
                float v0 = acc[mi][ni][half*2], v1 = acc[mi][ni][half*2 + 1];
                if (md == 2) { v0 *= inv[mi][half]; v1 *= inv[mi][half]; }
                if (md == 3) {
#pragma unroll
                    for (int e = 0; e < 2; e++) {
                        int cc = col + e;
                        float z = e ? v1 : v0;
                        if (cc < 16)      g_g [(size_t)row*HH + cc]        = sigmoidf_(z);
                        else if (cc < 32) g_f [(size_t)row*HH + cc - 16]   = sigmoidf_(z);
                        else if (cc < 96) g_g1[(size_t)row*HDIM + cc - 32] = z;
                    }
                } else {
                    *(float2*)(C + (size_t)row * DD + n0 + col) = make_float2(v0, v1);
                }
            }
        }
    }
}

// fused Q/K/V/small: tn 0-7 Q(silu), 8 small scatter, 9-16 K(silu+l2norm), 17-24 V(silu)
__global__ __launch_bounds__(256, 2) void gemm_qkv() {
    const int tn = blockIdx.x, m0 = blockIdx.y * 128;
    if (tn < 8)        gemm_core(g_xhi, g_xlo, g_wqhi, g_wqlo, g_q, 1, m0, tn*128);
    else if (tn == 8)  gemm_core(g_xhi, g_xlo, g_wshi, g_wslo, g_q, 3, m0, 0);
    else if (tn < 17)  gemm_core(g_xhi, g_xlo, g_wkhi, g_wklo, g_k, 2, m0, (tn-9)*128);
    else               gemm_core(g_xhi, g_xlo, g_wvhi, g_wvlo, g_v, 1, m0, (tn-17)*128);
}
__global__ __launch_bounds__(256, 2) void gemm_out(float* __restrict__ C) {
    gemm_core(g_nhi, g_nlo, g_wohi, g_wolo, C, 0, blockIdx.y * 128, blockIdx.x * 128);
}

// ---------------- gated delta-rule recurrence: 128 blocks, S[8]/lane ---------
// block = (b,h, col-quarter of 16). 4 warps x 4 cols; lane: col=(lane&3), rc=lane>>2.
__global__ __launch_bounds__(128) void recur_kernel() {
    __shared__ float ks[2][RT][64], qs[2][RT][64], vs[2][RT][16];
    __shared__ float fs[2][RT], gs_[2][RT];

    const int blk = blockIdx.x;
    const int bh = blk >> 2, qtr = blk & 3;
    const int b = bh >> 4, h = bh & 15;
    const int tid = threadIdx.x;
    const int w = tid >> 5, lane = tid & 31;
    const int col_local = w*4 + (lane & 3);
    const int col = qtr*16 + col_local;
    const int r0 = (lane >> 2) * 8;

    const size_t basev = (size_t)b * NNTOK * DD + h * HDIM;
    const size_t basef = (size_t)b * NNTOK * HH + h;

    auto stage = [&](int tile, int buf) {
        const int t0 = tile * RT;
#pragma unroll
        for (int p = 0; p < 4; p++) {
            int idx = tid + p * 128;
            int r = idx >> 4, i = (idx & 15) * 4;
            cp16(s2u(&ks[buf][r][i]), g_k + basev + (size_t)(t0 + r) * DD + i);
            cp16(s2u(&qs[buf][r][i]), g_q + basev + (size_t)(t0 + r) * DD + i);
        }
        {
            int r = tid >> 2, i = (tid & 3) * 4;
            cp16(s2u(&vs[buf][r][i]), g_v + basev + (size_t)(t0 + r) * DD + qtr*16 + i);
        }
        if (tid < RT)        cp4(s2u(&fs[buf][tid]),       g_f + basef + (size_t)(t0 + tid) * HH);
        else if (tid < 2*RT) cp4(s2u(&gs_[buf][tid - RT]), g_g + basef + (size_t)(t0 + tid - RT) * HH);
        asm volatile("cp.async.commit_group;" ::: "memory");
    };

    float S[8];
#pragma unroll
    for (int i = 0; i < 8; i++) S[i] = 0.f;

    auto loadkq = [&](int buf, int tt, float* kc, float* qc) {
#pragma unroll
        for (int i = 0; i < 2; i++) {
            float4 kv = *(const float4*)&ks[buf][tt][r0 + 4*i];
            float4 qv = *(const float4*)&qs[buf][tt][r0 + 4*i];
            kc[4*i] = kv.x; kc[4*i+1] = kv.y; kc[4*i+2] = kv.z; kc[4*i+3] = kv.w;
            qc[4*i] = qv.x; qc[4*i+1] = qv.y; qc[4*i+2] = qv.z; qc[4*i+3] = qv.w;
        }
    };

    auto dostep = [&](int buf, int t, int tt, const float* kc, const float* qc) {
        const float vc = vs[buf][tt][col_local];
        const float fc = fs[buf][tt];
        const float gv = gs_[buf][tt];
        const float cc0 = -gv * fc * fc;

        float p0 = 0.f, p1 = 0.f;
#pragma unroll
        for (int i = 0; i < 4; i++) {
            p0 = fmaf(kc[i],   S[i],   p0);
            p1 = fmaf(kc[i+4], S[i+4], p1);
        }
        float d = p0 + p1;
        d += __shfl_xor_sync(0xffffffffu, d, 4);
        d += __shfl_xor_sync(0xffffffffu, d, 8);
        d += __shfl_xor_sync(0xffffffffu, d, 16);

        const float u = fmaf(cc0, d, vc);
        float o0 = 0.f, o1 = 0.f;
#pragma unroll
        for (int i = 0; i < 4; i++) {
            S[i]   = fmaf(fc, S[i],   kc[i]   * u); o0 = fmaf(qc[i],   S[i],   o0);
            S[i+4] = fmaf(fc, S[i+4], kc[i+4] * u); o1 = fmaf(qc[i+4], S[i+4], o1);
        }
        float o = o0 + o1;
        o += __shfl_xor_sync(0xffffffffu, o, 4);
        o += __shfl_xor_sync(0xffffffffu, o, 8);
        o += __shfl_xor_sync(0xffffffffu, o, 16);
        if (lane < 4) g_o[basev + (size_t)t * DD + col] = o;
    };

    stage(0, 0);
    const int NT = NNTOK / RT;
    for (int tile = 0; tile < NT; tile++) {
        const int buf = tile & 1;
        __syncthreads();
        if (tile + 1 < NT) {
            stage(tile + 1, buf ^ 1);
            asm volatile("cp.async.wait_group 1;" ::: "memory");
        } else {
            asm volatile("cp.async.wait_group 0;" ::: "memory");
        }
        __syncthreads();

        const int t0 = tile * RT;
        float ka[8], qa[8], kb[8], qb[8];
        loadkq(buf, 0, ka, qa);
        for (int tt = 0; tt < RT; tt += 2) {
            if (tt + 1 < RT) loadkq(buf, tt + 1, kb, qb);
            dostep(buf, t0 + tt, tt, ka, qa);
            if (tt + 2 < RT) loadkq(buf, tt + 2, ka, qa);
            dostep(buf, t0 + tt + 1, tt + 1, kb, qb);
        }
    }
}

// -------- gate + LayerNorm -> bf16 hi/lo split -------------------------------
__global__ __launch_bounds__(256) void gate_ln_kernel(const float* __restrict__ Wg2,
                                                      const float* __restrict__ nw) {
    __shared__ float g1s[8 * 64];
    __shared__ float rb[8 * 1024];
    const int row0 = blockIdx.x * 8;
    const int tid = threadIdx.x;
    for (int i = tid; i < 512; i += 256) g1s[i] = g_g1[(size_t)row0 * 64 + i];
    __syncthreads();
#pragma unroll
    for (int cs = 0; cs < 4; cs++) {
        const int c = tid + cs * 256;
        float a[8];
#pragma unroll
        for (int r = 0; r < 8; r++) a[r] = 0.f;
#pragma unroll 4
        for (int k = 0; k < 64; k++) {
            float wv = Wg2[(size_t)k * DD + c];
#pragma unroll
            for (int r = 0; r < 8; r++) a[r] = fmaf(g1s[r * 64 + k], wv, a[r]);
        }
#pragma unroll
        for (int r = 0; r < 8; r++)
            rb[r * 1024 + c] = g_o[(size_t)(row0 + r) * DD + c] * sigmoidf_(a[r]);
    }
    __syncthreads();
    const int wr = tid >> 5, ln = tid & 31;
    float s = 0.f, s2 = 0.f;
#pragma unroll 8
    for (int i = 0; i < 32; i++) {
        float v = rb[wr * 1024 + ln + 32 * i];
        s += v; s2 = fmaf(v, v, s2);
    }
#pragma unroll
    for (int o = 16; o; o >>= 1) {
        s  += __shfl_xor_sync(0xffffffffu, s,  o);
        s2 += __shfl_xor_sync(0xffffffffu, s2, o);
    }
    const float mu = s * (1.f / 1024.f);
    const float rstd = rsqrtf(s2 * (1.f / 1024.f) - mu * mu + 1e-5f);
#pragma unroll 8
    for (int i = 0; i < 32; i++) {
        int c = ln + 32 * i;
        float v = (rb[wr * 1024 + c] - mu) * rstd * nw[c];
        __nv_bfloat16 hi = __float2bfloat16(v);
        size_t idx = (size_t)(row0 + wr) * DD + c;
        g_nhi[idx] = hi;
        g_nlo[idx] = __float2bfloat16(v - __bfloat162float(hi));
    }
}

// -----------------------------------------------------------------------------
extern "C" void kernel_launch(void* const* d_in, const int* in_sizes, int n_in,
                              void* d_out, int out_size) {
    const float* x      = (const float*)d_in[0];
    const float* Wq     = (const float*)d_in[1];
    const float* Wk     = (const float*)d_in[2];
    const float* Wv     = (const float*)d_in[3];
    const float* Wgamma = (const float*)d_in[4];
    const float* Wf     = (const float*)d_in[5];
    const float* Wg1    = (const float*)d_in[6];
    const float* Wg2    = (const float*)d_in[7];
    const float* Wo     = (const float*)d_in[8];
    const float* norm_w = (const float*)d_in[9];
    float* out = (float*)d_out;

    cudaFuncSetAttribute(gemm_qkv, cudaFuncAttributeMaxDynamicSharedMemorySize, GSMEM);
    cudaFuncSetAttribute(gemm_out, cudaFuncAttributeMaxDynamicSharedMemorySize, GSMEM);

    prep_kernel<<<16384 + 4096 + 128, 256>>>(x, Wq, Wk, Wv, Wo, Wgamma, Wf, Wg1);
    gemm_qkv<<<dim3(25, 32), 256, GSMEM>>>();
    recur_kernel<<<128, 128>>>();
    gate_ln_kernel<<<BN/8, 256>>>(Wg2, norm_w);
    gemm_out<<<dim3(8, 32), 256, GSMEM>>>(out);
}